// round 5
// baseline (speedup 1.0000x reference)
#include <cuda_runtime.h>
#include <cuda_fp16.h>
#include <cstdint>

#define NN   50000
#define NE   800000
#define FIN  128
#define FHID 384
#define FOUT 256

// ----------------------------- scratch --------------------------------------
__device__ float  g_agg1[NN * FIN];            // 25.6 MB
__device__ float  g_x1[(size_t)NN * FHID];     // 76.8 MB
__device__ __half g_y_h[(size_t)NN * FOUT];    // 25.6 MB
__device__ __half g_feat_h[NN * FIN];          // 12.8 MB (features * out_norm, fp16)
__device__ int    g_deg[2 * NN];               // [0..NN) = deg_out, [NN..2NN) = deg_in
__device__ float  g_out_norm[NN];
__device__ float  g_in_norm[NN];
__device__ int    g_off[NN + 1];
__device__ int    g_cursor[NN];
__device__ int    g_csr_src[NE];

// ----------------------------- helpers --------------------------------------
__device__ __forceinline__ unsigned f2tf32(float x) {
    unsigned r;
    asm("cvt.rna.tf32.f32 %0, %1;" : "=r"(r) : "f"(x));
    return r;
}

__device__ __forceinline__ void mma_tf32(float& c0, float& c1, float& c2, float& c3,
                                         unsigned a0, unsigned a1, unsigned a2, unsigned a3,
                                         unsigned b0, unsigned b1) {
    asm volatile("mma.sync.aligned.m16n8k8.row.col.f32.tf32.tf32.f32 "
                 "{%0,%1,%2,%3}, {%4,%5,%6,%7}, {%8,%9}, {%0,%1,%2,%3};"
                 : "+f"(c0), "+f"(c1), "+f"(c2), "+f"(c3)
                 : "r"(a0), "r"(a1), "r"(a2), "r"(a3), "r"(b0), "r"(b1));
}

__device__ __forceinline__ __half2 bits2h(unsigned u) {
    return *reinterpret_cast<__half2*>(&u);
}

// ----------------------------- prelude kernels -------------------------------
__global__ void zero_deg_kernel(int* __restrict__ p) {
    int i = blockIdx.x * blockDim.x + threadIdx.x;
    if (i < 2 * NN) p[i] = 0;
}

__global__ void degree_kernel(const int* __restrict__ ei, int* __restrict__ deg) {
    int e = blockIdx.x * blockDim.x + threadIdx.x;
    if (e < NE) {
        atomicAdd(&deg[ei[e]], 1);            // deg_out
        atomicAdd(&deg[NN + ei[NE + e]], 1);  // deg_in
    }
}

// Single-block exclusive scan over deg_in -> off, cursor.
__global__ void scan_kernel(const int* __restrict__ deg,
                            int* __restrict__ off, int* __restrict__ cursor) {
    constexpr int T = 1024;
    constexpr int CHUNK = (NN + T - 1) / T;   // 49
    const int* din = deg + NN;
    __shared__ int ssum[T];
    int t = threadIdx.x;
    int base = t * CHUNK;
    int s = 0;
#pragma unroll 4
    for (int i = 0; i < CHUNK; i++) {
        int idx = base + i;
        if (idx < NN) s += din[idx];
    }
    ssum[t] = s;
    __syncthreads();
    for (int d = 1; d < T; d <<= 1) {
        int v = (t >= d) ? ssum[t - d] : 0;
        __syncthreads();
        if (t >= d) ssum[t] += v;
        __syncthreads();
    }
    int run = (t > 0) ? ssum[t - 1] : 0;
    for (int i = 0; i < CHUNK; i++) {
        int idx = base + i;
        if (idx < NN) {
            off[idx] = run;
            cursor[idx] = run;
            run += din[idx];
        }
    }
    if (t == T - 1) off[NN] = NE;
}

__global__ void scatter_kernel(const int* __restrict__ ei,
                               int* __restrict__ cursor,
                               int* __restrict__ csr_src) {
    int e = blockIdx.x * blockDim.x + threadIdx.x;
    if (e < NE) {
        int src = ei[e];
        int dst = ei[NE + e];
        int pos = atomicAdd(&cursor[dst], 1);
        csr_src[pos] = src;
    }
}

// norms + feat_h = fp16(features * out_norm[row]) in one kernel.
__global__ void norm_f2h_kernel(const int* __restrict__ deg,
                                const float* __restrict__ feat,
                                float* __restrict__ onorm, float* __restrict__ inorm,
                                __half* __restrict__ feat_h) {
    int i = blockIdx.x * blockDim.x + threadIdx.x;
    if (i < NN) {
        onorm[i] = rsqrtf((float)max(deg[i], 1));
        inorm[i] = rsqrtf((float)max(deg[NN + i], 1));
    }
    const int n4 = NN * (FIN / 4);
    if (i < n4) {
        int row = i >> 5;                       // FIN/4 = 32
        float s = rsqrtf((float)max(__ldg(&deg[row]), 1));
        float4 v = ((const float4*)feat)[i];
        __half2 h0 = __floats2half2_rn(v.x * s, v.y * s);
        __half2 h1 = __floats2half2_rn(v.z * s, v.w * s);
        ((uint2*)feat_h)[i] = make_uint2(*(unsigned*)&h0, *(unsigned*)&h1);
    }
}

// ----------------------------- gathers (MLP x4) ------------------------------
// agg1[n] = sum_{src in N(n)} feat_h[src]   (feat_h pre-scaled by out_norm)
__global__ void agg1_gather_kernel(const int* __restrict__ off,
                                   const int* __restrict__ csr_src,
                                   const __half* __restrict__ feat,
                                   float* __restrict__ agg) {
    int n = (blockIdx.x * blockDim.x + threadIdx.x) >> 5;
    if (n >= NN) return;
    int lane = threadIdx.x & 31;
    int beg = off[n], end = off[n + 1];
    float4 acc = make_float4(0.f, 0.f, 0.f, 0.f);
    for (int j = beg; j < end; j += 32) {
        int m = min(32, end - j);
        int s = (lane < m) ? __ldg(&csr_src[j + lane]) : 0;
        int k = 0;
        for (; k + 4 <= m; k += 4) {
            int s0 = __shfl_sync(0xffffffffu, s, k + 0);
            int s1 = __shfl_sync(0xffffffffu, s, k + 1);
            int s2 = __shfl_sync(0xffffffffu, s, k + 2);
            int s3 = __shfl_sync(0xffffffffu, s, k + 3);
            uint2 u0 = __ldg((const uint2*)(feat + (size_t)s0 * FIN + lane * 4));
            uint2 u1 = __ldg((const uint2*)(feat + (size_t)s1 * FIN + lane * 4));
            uint2 u2 = __ldg((const uint2*)(feat + (size_t)s2 * FIN + lane * 4));
            uint2 u3 = __ldg((const uint2*)(feat + (size_t)s3 * FIN + lane * 4));
            float2 a, b;
            a = __half22float2(bits2h(u0.x)); b = __half22float2(bits2h(u0.y));
            acc.x += a.x; acc.y += a.y; acc.z += b.x; acc.w += b.y;
            a = __half22float2(bits2h(u1.x)); b = __half22float2(bits2h(u1.y));
            acc.x += a.x; acc.y += a.y; acc.z += b.x; acc.w += b.y;
            a = __half22float2(bits2h(u2.x)); b = __half22float2(bits2h(u2.y));
            acc.x += a.x; acc.y += a.y; acc.z += b.x; acc.w += b.y;
            a = __half22float2(bits2h(u3.x)); b = __half22float2(bits2h(u3.y));
            acc.x += a.x; acc.y += a.y; acc.z += b.x; acc.w += b.y;
        }
        for (; k < m; k++) {
            int ss = __shfl_sync(0xffffffffu, s, k);
            uint2 u = __ldg((const uint2*)(feat + (size_t)ss * FIN + lane * 4));
            float2 a = __half22float2(bits2h(u.x));
            float2 b = __half22float2(bits2h(u.y));
            acc.x += a.x; acc.y += a.y; acc.z += b.x; acc.w += b.y;
        }
    }
    *(float4*)(agg + (size_t)n * FIN + lane * 4) = acc;
}

// out[n] = inorm[n] * sum_{src in N(n)} y_h[src] + b2
__global__ void agg2_gather_kernel(const int* __restrict__ off,
                                   const int* __restrict__ csr_src,
                                   const __half* __restrict__ y,
                                   const float* __restrict__ inorm,
                                   const float* __restrict__ b2,
                                   float* __restrict__ out) {
    int n = (blockIdx.x * blockDim.x + threadIdx.x) >> 5;
    if (n >= NN) return;
    int lane = threadIdx.x & 31;
    int beg = off[n], end = off[n + 1];
    float acc[8] = {0.f, 0.f, 0.f, 0.f, 0.f, 0.f, 0.f, 0.f};
    for (int j = beg; j < end; j += 32) {
        int m = min(32, end - j);
        int s = (lane < m) ? __ldg(&csr_src[j + lane]) : 0;
        int k = 0;
        for (; k + 2 <= m; k += 2) {
            int s0 = __shfl_sync(0xffffffffu, s, k + 0);
            int s1 = __shfl_sync(0xffffffffu, s, k + 1);
            uint4 u0 = __ldg((const uint4*)(y + (size_t)s0 * FOUT + lane * 8));
            uint4 u1 = __ldg((const uint4*)(y + (size_t)s1 * FOUT + lane * 8));
            float2 f;
            f = __half22float2(bits2h(u0.x)); acc[0] += f.x; acc[1] += f.y;
            f = __half22float2(bits2h(u0.y)); acc[2] += f.x; acc[3] += f.y;
            f = __half22float2(bits2h(u0.z)); acc[4] += f.x; acc[5] += f.y;
            f = __half22float2(bits2h(u0.w)); acc[6] += f.x; acc[7] += f.y;
            f = __half22float2(bits2h(u1.x)); acc[0] += f.x; acc[1] += f.y;
            f = __half22float2(bits2h(u1.y)); acc[2] += f.x; acc[3] += f.y;
            f = __half22float2(bits2h(u1.z)); acc[4] += f.x; acc[5] += f.y;
            f = __half22float2(bits2h(u1.w)); acc[6] += f.x; acc[7] += f.y;
        }
        for (; k < m; k++) {
            int ss = __shfl_sync(0xffffffffu, s, k);
            uint4 u = __ldg((const uint4*)(y + (size_t)ss * FOUT + lane * 8));
            float2 f;
            f = __half22float2(bits2h(u.x)); acc[0] += f.x; acc[1] += f.y;
            f = __half22float2(bits2h(u.y)); acc[2] += f.x; acc[3] += f.y;
            f = __half22float2(bits2h(u.z)); acc[4] += f.x; acc[5] += f.y;
            f = __half22float2(bits2h(u.w)); acc[6] += f.x; acc[7] += f.y;
        }
    }
    float sc = __ldg(&inorm[n]);
    float4 bb0 = *(const float4*)(b2 + lane * 8);
    float4 bb1 = *(const float4*)(b2 + lane * 8 + 4);
    float4 o0, o1;
    o0.x = acc[0] * sc + bb0.x; o0.y = acc[1] * sc + bb0.y;
    o0.z = acc[2] * sc + bb0.z; o0.w = acc[3] * sc + bb0.w;
    o1.x = acc[4] * sc + bb1.x; o1.y = acc[5] * sc + bb1.y;
    o1.z = acc[6] * sc + bb1.z; o1.w = acc[7] * sc + bb1.w;
    float* orow = out + (size_t)n * FOUT + lane * 8;
    *(float4*)orow = o0;
    *(float4*)(orow + 4) = o1;
}

// ----------------------------- tf32 tensor GEMM ------------------------------
// Fragment-order smem layout:
//  AsF [mTile(8)][kTile(4)][lane(32)][slot(4)]  (lane XOR mTile swizzle)
//  BsF [kTile(4)][nTile(8)][lane(32)][slot(2)]
// Inner loop: LDS.128 A-frags, LDS.64 B-frags. Double buffered, 1 barrier/K-tile.
template<bool RELU, bool HAS_BIAS, bool OUT_HALF>
__global__ __launch_bounds__(256)
void gemm_tf32_kernel(const float* __restrict__ A, const float* __restrict__ B,
                      void* __restrict__ Cv,
                      const float* __restrict__ rowscale,
                      const float* __restrict__ bias,
                      int M, int N, int K) {
    constexpr int BM = 128, BN = 64, BK = 32;
    __shared__ unsigned AsF[2][4096];   // 16KB x2
    __shared__ unsigned BsF[2][2048];   // 8KB x2

    const int tid  = threadIdx.x;
    const int warp = tid >> 5;
    const int lane = tid & 31;
    const int wm = warp & 3;
    const int wn = warp >> 2;

    const int brow0 = blockIdx.y * BM;
    const int bcol0 = blockIdx.x * BN;

    // A staging coords: mt_s fastest so STS quarter-warps span mTile (XOR swizzle works)
    const int a_mt  = tid & 7;            // mTile 0..7
    const int a_kt  = (tid >> 3) & 3;     // kTile 0..3
    const int a_gid = tid >> 5;           // 0..7
    const int arow0 = brow0 + a_mt * 16 + a_gid;
    const int arow1 = arow0 + 8;

    // B staging coords
    const int b_kt  = tid >> 6;           // 0..3
    const int b_nt  = (tid >> 3) & 7;     // 0..7
    const int b_gid = tid & 7;            // 0..7
    const int b_n   = bcol0 + b_nt * 8 + b_gid;

    float acc[2][4][4];
#pragma unroll
    for (int mt = 0; mt < 2; mt++)
#pragma unroll
        for (int nt = 0; nt < 4; nt++)
#pragma unroll
            for (int f = 0; f < 4; f++) acc[mt][nt][f] = 0.f;

    float4 ra0, ra1, ra2, ra3;            // row0 k0-3, row0 k4-7, row1 k0-3, row1 k4-7
    float rb[8];

    auto load_tile = [&](int k0) {
        const float* a0p = A + (size_t)arow0 * K + k0 + a_kt * 8;
        const float* a1p = A + (size_t)arow1 * K + k0 + a_kt * 8;
        ra0 = ra1 = ra2 = ra3 = make_float4(0.f, 0.f, 0.f, 0.f);
        if (arow0 < M) { ra0 = *(const float4*)a0p; ra1 = *(const float4*)(a0p + 4); }
        if (arow1 < M) { ra2 = *(const float4*)a1p; ra3 = *(const float4*)(a1p + 4); }
        const float* bp = B + (size_t)(k0 + b_kt * 8) * N + b_n;
#pragma unroll
        for (int e = 0; e < 8; e++) rb[e] = __ldg(bp + (size_t)e * N);
    };

    auto store_tile = [&](int buf) {
        // A: 4 x STS.128, lane-XOR-mTile swizzle
        unsigned regionA = (a_mt * 4 + a_kt) * 128;
        float r0[8] = {ra0.x, ra0.y, ra0.z, ra0.w, ra1.x, ra1.y, ra1.z, ra1.w};
        float r1[8] = {ra2.x, ra2.y, ra2.z, ra2.w, ra3.x, ra3.y, ra3.z, ra3.w};
#pragma unroll
        for (int g = 0; g < 4; g++) {
            int lp = (a_gid * 4 + g) ^ a_mt;
            uint4 q;
            q.x = f2tf32(r0[g]);     // slot0: (row0, k=g)
            q.y = f2tf32(r1[g]);     // slot1: (row1, k=g)
            q.z = f2tf32(r0[g + 4]); // slot2: (row0, k=g+4)
            q.w = f2tf32(r1[g + 4]); // slot3: (row1, k=g+4)
            *(uint4*)&AsF[buf][regionA + lp * 4] = q;
        }
        // B: 2 x STS.128
        unsigned baseB = (b_kt * 8 + b_nt) * 64 + b_gid * 8;
        uint4 q0, q1;
        q0.x = f2tf32(rb[0]); q0.y = f2tf32(rb[4]); q0.z = f2tf32(rb[1]); q0.w = f2tf32(rb[5]);
        q1.x = f2tf32(rb[2]); q1.y = f2tf32(rb[6]); q1.z = f2tf32(rb[3]); q1.w = f2tf32(rb[7]);
        *(uint4*)&BsF[buf][baseB]     = q0;
        *(uint4*)&BsF[buf][baseB + 4] = q1;
    };

    load_tile(0);
    int buf = 0;

    for (int k0 = 0; k0 < K; k0 += BK) {
        store_tile(buf);
        __syncthreads();
        if (k0 + BK < K) load_tile(k0 + BK);

#pragma unroll
        for (int ksi = 0; ksi < 4; ksi++) {
            uint4 a[2];
#pragma unroll
            for (int mt = 0; mt < 2; mt++) {
                int mTile = wm * 2 + mt;
                a[mt] = *(const uint4*)&AsF[buf][(mTile * 4 + ksi) * 128 + (lane ^ mTile) * 4];
            }
            uint2 b[4];
#pragma unroll
            for (int nt = 0; nt < 4; nt++)
                b[nt] = *(const uint2*)&BsF[buf][(ksi * 8 + wn * 4 + nt) * 64 + lane * 2];
#pragma unroll
            for (int mt = 0; mt < 2; mt++)
#pragma unroll
                for (int nt = 0; nt < 4; nt++)
                    mma_tf32(acc[mt][nt][0], acc[mt][nt][1],
                             acc[mt][nt][2], acc[mt][nt][3],
                             a[mt].x, a[mt].y, a[mt].z, a[mt].w,
                             b[nt].x, b[nt].y);
        }
        buf ^= 1;
    }

    // ---- Epilogue
    const int gid = lane >> 2;
    const int tig = lane & 3;
#pragma unroll
    for (int mt = 0; mt < 2; mt++) {
        int r0 = brow0 + wm * 32 + mt * 16 + gid;
        int r1 = r0 + 8;
        float rs0 = (r0 < M) ? __ldg(&rowscale[r0]) : 0.f;
        float rs1 = (r1 < M) ? __ldg(&rowscale[r1]) : 0.f;
#pragma unroll
        for (int nt = 0; nt < 4; nt++) {
            int c = bcol0 + wn * 32 + nt * 8 + 2 * tig;
            float2 bb = make_float2(0.f, 0.f);
            if (HAS_BIAS) bb = *(const float2*)(bias + c);
            float2 o0, o1;
            o0.x = acc[mt][nt][0] * rs0 + bb.x;
            o0.y = acc[mt][nt][1] * rs0 + bb.y;
            o1.x = acc[mt][nt][2] * rs1 + bb.x;
            o1.y = acc[mt][nt][3] * rs1 + bb.y;
            if (RELU) {
                o0.x = fmaxf(o0.x, 0.f); o0.y = fmaxf(o0.y, 0.f);
                o1.x = fmaxf(o1.x, 0.f); o1.y = fmaxf(o1.y, 0.f);
            }
            if (OUT_HALF) {
                __half* C = (__half*)Cv;
                if (r0 < M) *(__half2*)(C + (size_t)r0 * N + c) = __floats2half2_rn(o0.x, o0.y);
                if (r1 < M) *(__half2*)(C + (size_t)r1 * N + c) = __floats2half2_rn(o1.x, o1.y);
            } else {
                float* C = (float*)Cv;
                if (r0 < M) *(float2*)(C + (size_t)r0 * N + c) = o0;
                if (r1 < M) *(float2*)(C + (size_t)r1 * N + c) = o1;
            }
        }
    }
}

// ----------------------------- launch ---------------------------------------
extern "C" void kernel_launch(void* const* d_in, const int* in_sizes, int n_in,
                              void* d_out, int out_size) {
    const float *features = nullptr, *W1 = nullptr, *b1 = nullptr,
                *W2 = nullptr, *b2 = nullptr;
    const int* ei = nullptr;
    for (int i = 0; i < n_in; i++) {
        switch (in_sizes[i]) {
            case NN * FIN:      features = (const float*)d_in[i]; break;
            case FIN * FHID:    W1 = (const float*)d_in[i]; break;
            case FHID:          b1 = (const float*)d_in[i]; break;
            case FHID * FOUT:   W2 = (const float*)d_in[i]; break;
            case FOUT:          b2 = (const float*)d_in[i]; break;
            case 2 * NE:        ei = (const int*)d_in[i]; break;
            default: break;
        }
    }
    float* out = (float*)d_out;

    float *agg1, *x1, *onorm, *inorm;
    __half *y_h, *feat_h;
    int *deg, *off, *cursor, *csr_src;
    cudaGetSymbolAddress((void**)&agg1,    g_agg1);
    cudaGetSymbolAddress((void**)&x1,      g_x1);
    cudaGetSymbolAddress((void**)&y_h,     g_y_h);
    cudaGetSymbolAddress((void**)&feat_h,  g_feat_h);
    cudaGetSymbolAddress((void**)&onorm,   g_out_norm);
    cudaGetSymbolAddress((void**)&inorm,   g_in_norm);
    cudaGetSymbolAddress((void**)&deg,     g_deg);
    cudaGetSymbolAddress((void**)&off,     g_off);
    cudaGetSymbolAddress((void**)&cursor,  g_cursor);
    cudaGetSymbolAddress((void**)&csr_src, g_csr_src);

    const int T = 256;

    // [1] zero degree counters
    zero_deg_kernel<<<(2 * NN + T - 1) / T, T>>>(deg);
    // [2] degrees
    degree_kernel<<<(NE + T - 1) / T, T>>>(ei, deg);
    // [3] scan (offsets + cursors)
    scan_kernel<<<1, 1024>>>(deg, off, cursor);
    // [4] counting-sort scatter
    scatter_kernel<<<(NE + T - 1) / T, T>>>(ei, cursor, csr_src);
    // [5] norms + scaled fp16 features
    {
        int n4 = NN * FIN / 4;
        norm_f2h_kernel<<<(n4 + T - 1) / T, T>>>(deg, features, onorm, inorm, feat_h);
    }
    // [6] agg1 = gather(feat_h)   [NN, 128]    <-- ncu -s 5 lands here
    {
        long long threads = (long long)NN * 32;
        agg1_gather_kernel<<<(unsigned)((threads + T - 1) / T), T>>>(
            off, csr_src, feat_h, agg1);
    }
    // [7] x1 = relu( inorm[row] * (agg1 @ W1) + b1 )
    {
        dim3 grid(FHID / 64, (NN + 127) / 128);
        gemm_tf32_kernel<true, true, false><<<grid, 256>>>(agg1, W1, x1, inorm, b1,
                                                           NN, FHID, FIN);
    }
    // [8] y_h = fp16( onorm[row] * (x1 @ W2) )
    {
        dim3 grid(FOUT / 64, (NN + 127) / 128);
        gemm_tf32_kernel<false, false, true><<<grid, 256>>>(x1, W2, y_h, onorm, nullptr,
                                                            NN, FOUT, FHID);
    }
    // [9] out = inorm[row] * gather(y_h) + b2
    {
        long long threads = (long long)NN * 32;
        agg2_gather_kernel<<<(unsigned)((threads + T - 1) / T), T>>>(
            off, csr_src, y_h, inorm, b2, out);
    }
}